// round 5
// baseline (speedup 1.0000x reference)
#include <cuda_runtime.h>
#include <cuda_bf16.h>
#include <mma.h>
#include <math.h>

using namespace nvcuda;

#define D_DIM 128
#define V_DIM 100000
#define N_DIM 20000
#define E_DIM 640000
#define NODES_PER_BLK 64
#define NTILES ((N_DIM + NODES_PER_BLK - 1) / NODES_PER_BLK)   // 313

// padded strides (conflict-free LDSM: 528B row shift = 4 banks)
#define SA 264                 // bf16 elems per A row (528 B)
#define SC 132                 // float elems per C row (528 B)
#define A_BYTES (64 * SA * 2)  // 33792 (== 64*SC*4, C overlays A)

// prep kernel block ranges
#define EPACK_BLOCKS 12500     // 12.8M floats / (256 thr * 4 floats)
#define WM_BLOCKS    32        // 32768 elems / (256 thr * 4)
#define RP_BLOCKS    2500      // 640000 / 256
#define PREP_BLOCKS  (EPACK_BLOCKS + WM_BLOCKS + RP_BLOCKS)

// ---------------- scratch (device globals; no runtime allocation) ----------
__device__ int   g_rowptr[N_DIM + 1];
__device__ __nv_bfloat16 g_embh[(size_t)V_DIM * D_DIM];      // 25.6 MB bf16 table
__device__ __nv_bfloat16 g_wm[D_DIM * 2 * D_DIM];            // [128][256] bf16
__device__ float g_partials[NTILES * D_DIM];

// ---------------- K1: prep (pack emb->bf16, pack [W|M], rowptr) ------------
__global__ void prep_kernel(const float* __restrict__ emb,
                            const float* __restrict__ W,
                            const float* __restrict__ M,
                            const int* __restrict__ seg) {
    const int b   = blockIdx.x;
    const int tid = threadIdx.x;

    if (b < EPACK_BLOCKS) {
        // pack embedding table: one float4 -> uint2 (4 bf16) per thread
        int i = b * 256 + tid;                    // float4 index, 3.2M total
        float4 v = __ldg(((const float4*)emb) + i);
        __nv_bfloat162 lo = __float22bfloat162_rn(make_float2(v.x, v.y));
        __nv_bfloat162 hi = __float22bfloat162_rn(make_float2(v.z, v.w));
        uint2 u;
        u.x = *(unsigned int*)&lo;
        u.y = *(unsigned int*)&hi;
        ((uint2*)g_embh)[i] = u;
    } else if (b < EPACK_BLOCKS + WM_BLOCKS) {
        int base = (b - EPACK_BLOCKS) * 256 + tid;
        #pragma unroll
        for (int rep = 0; rep < 4; ++rep) {
            int i = base + rep * 8192;            // 0..32767
            int d = i >> 8;
            int k = i & 255;
            float v = (k < D_DIM) ? __ldg(&W[d * D_DIM + k])
                                  : __ldg(&M[d * D_DIM + (k - D_DIM)]);
            g_wm[i] = __float2bfloat16(v);
        }
    } else {
        int e = (b - EPACK_BLOCKS - WM_BLOCKS) * 256 + tid;
        if (e >= E_DIM) return;
        int s = __ldg(&seg[e]);
        if (e == 0) {
            for (int t = 0; t <= s; ++t) g_rowptr[t] = 0;
        } else {
            int p = __ldg(&seg[e - 1]);
            for (int t = p + 1; t <= s; ++t) g_rowptr[t] = e;
        }
        if (e == E_DIM - 1) {
            for (int t = s + 1; t <= N_DIM; ++t) g_rowptr[t] = E_DIM;
        }
    }
}

// ---------------- helpers ---------------------------------------------------
__device__ __forceinline__ void acc_bf8(float acc[8], uint4 v) {
    __nv_bfloat162 b0 = *(__nv_bfloat162*)&v.x;
    __nv_bfloat162 b1 = *(__nv_bfloat162*)&v.y;
    __nv_bfloat162 b2 = *(__nv_bfloat162*)&v.z;
    __nv_bfloat162 b3 = *(__nv_bfloat162*)&v.w;
    float2 f0 = __bfloat1622float2(b0);
    float2 f1 = __bfloat1622float2(b1);
    float2 f2 = __bfloat1622float2(b2);
    float2 f3 = __bfloat1622float2(b3);
    acc[0] += f0.x; acc[1] += f0.y;
    acc[2] += f1.x; acc[3] += f1.y;
    acc[4] += f2.x; acc[5] += f2.y;
    acc[6] += f3.x; acc[7] += f3.y;
}

__device__ __forceinline__ uint4 pack_bf8(const float acc[8]) {
    __nv_bfloat162 b0 = __float22bfloat162_rn(make_float2(acc[0], acc[1]));
    __nv_bfloat162 b1 = __float22bfloat162_rn(make_float2(acc[2], acc[3]));
    __nv_bfloat162 b2 = __float22bfloat162_rn(make_float2(acc[4], acc[5]));
    __nv_bfloat162 b3 = __float22bfloat162_rn(make_float2(acc[6], acc[7]));
    uint4 u;
    u.x = *(unsigned int*)&b0;
    u.y = *(unsigned int*)&b1;
    u.z = *(unsigned int*)&b2;
    u.w = *(unsigned int*)&b3;
    return u;
}

// ---------------- K2: FUSED gather + segment-sum + GEMM + relu + colsum ----
// One block per 64-node tile, 512 threads = 16 warps.
// Phase 1: warp w owns rows [4w,4w+4). bf16 table rows are 256B; the warp
//   splits into 2 half-warps (slot = lane>>4), each half owning one edge of a
//   pair per LDG.128 (lane&15 = 16B chunk). fp32 accumulate, shfl_xor(16)
//   combine, pack to bf16 A tile. Self row is a straight bf16 copy.
// Phase 2: warp w: rows [32(w>>3), +32), cols [16(w&7), +16). B from g_wm.
// Phase 3: relu -> C overlay -> column-sum -> per-block partials.
__global__ __launch_bounds__(512)
void fused_kernel(const int* __restrict__ node_ids,
                  const int* __restrict__ nbr) {
    extern __shared__ unsigned char dynsmem[];
    __nv_bfloat16* As = (__nv_bfloat16*)dynsmem;   // [64][SA]
    float*         Cs = (float*)dynsmem;           // [64][SC] (overlay)
    __shared__ float red[512];

    const int tid  = threadIdx.x;
    const int w    = tid >> 5;
    const int lane = tid & 31;
    const int slot = lane >> 4;    // half-warp edge slot (0/1)
    const int c    = lane & 15;    // 16B chunk within 256B row
    const int n0   = blockIdx.x * NODES_PER_BLK;

    // ---------- Phase 1: gather + aggregate into A (bf16 table) ----------
    #pragma unroll
    for (int i = 0; i < 4; ++i) {
        const int r = w * 4 + i;
        const int n = n0 + r;
        const bool valid = (n < N_DIM);

        // self row: bf16 -> bf16 copy (lanes 0..15)
        if (slot == 0) {
            uint4 sv = make_uint4(0, 0, 0, 0);
            if (valid) {
                int nid = __ldg(&node_ids[n]);
                sv = __ldg(((const uint4*)(g_embh + (size_t)nid * D_DIM)) + c);
            }
            *(uint4*)(As + r * SA + c * 8) = sv;
        }

        float acc[8] = {0.f, 0.f, 0.f, 0.f, 0.f, 0.f, 0.f, 0.f};
        if (valid) {
            const int s = g_rowptr[n];
            const int e = g_rowptr[n + 1];
            int j = s;
            // 4 edges per iteration (2 per half-warp), 2 gathers in flight
            for (; j + 4 <= e; j += 4) {
                int i0 = __ldg(&nbr[j + slot]);
                int i1 = __ldg(&nbr[j + 2 + slot]);
                uint4 v0 = __ldg(((const uint4*)(g_embh + (size_t)i0 * D_DIM)) + c);
                uint4 v1 = __ldg(((const uint4*)(g_embh + (size_t)i1 * D_DIM)) + c);
                acc_bf8(acc, v0);
                acc_bf8(acc, v1);
            }
            for (; j < e; j += 2) {
                int edge = j + slot;
                if (edge < e) {
                    int ix = __ldg(&nbr[edge]);
                    uint4 v = __ldg(((const uint4*)(g_embh + (size_t)ix * D_DIM)) + c);
                    acc_bf8(acc, v);
                }
            }
        }
        // combine the two half-warps
        #pragma unroll
        for (int t = 0; t < 8; ++t)
            acc[t] += __shfl_xor_sync(0xffffffffu, acc[t], 16);
        if (slot == 0)
            *(uint4*)(As + r * SA + D_DIM + c * 8) = pack_bf8(acc);
    }
    __syncthreads();

    // ---------- Phase 2: MMA ----------
    const int rb = w >> 3;    // rows [32rb, 32rb+32)
    const int cb = w & 7;     // cols [16cb, 16cb+16)

    wmma::fragment<wmma::accumulator, 16, 16, 16, float> c0f, c1f;
    wmma::fill_fragment(c0f, 0.0f);
    wmma::fill_fragment(c1f, 0.0f);

    #pragma unroll
    for (int kk = 0; kk < 16; ++kk) {
        wmma::fragment<wmma::matrix_b, 16, 16, 16, __nv_bfloat16, wmma::col_major> bf;
        wmma::load_matrix_sync(bf, g_wm + (cb * 16) * 256 + kk * 16, 256);
        wmma::fragment<wmma::matrix_a, 16, 16, 16, __nv_bfloat16, wmma::row_major> a0, a1;
        wmma::load_matrix_sync(a0, As + (rb * 32) * SA + kk * 16, SA);
        wmma::load_matrix_sync(a1, As + (rb * 32 + 16) * SA + kk * 16, SA);
        wmma::mma_sync(c0f, a0, bf, c0f);
        wmma::mma_sync(c1f, a1, bf, c1f);
    }
    __syncthreads();    // all warps done reading A before C overlay

    #pragma unroll
    for (int t = 0; t < c0f.num_elements; ++t) {
        c0f.x[t] = fmaxf(c0f.x[t], 0.0f);
        c1f.x[t] = fmaxf(c1f.x[t], 0.0f);
    }
    wmma::store_matrix_sync(Cs + (rb * 32) * SC + cb * 16, c0f, SC, wmma::mem_row_major);
    wmma::store_matrix_sync(Cs + (rb * 32 + 16) * SC + cb * 16, c1f, SC, wmma::mem_row_major);
    __syncthreads();

    // ---------- Phase 3: column-sum 64x128 -> partials ----------
    {
        const int col  = tid & 127;
        const int part = tid >> 7;        // 0..3 -> 16-row bands
        float s = 0.f;
        #pragma unroll
        for (int rr = part * 16; rr < part * 16 + 16; ++rr)
            s += Cs[rr * SC + col];
        red[tid] = s;
    }
    __syncthreads();
    if (tid < 128)
        g_partials[blockIdx.x * D_DIM + tid] =
            red[tid] + red[tid + 128] + red[tid + 256] + red[tid + 384];
}

// ---------------- K3: reduce partials + softmax (float4, warp-parallel) ----
__global__ void final_kernel(float* __restrict__ out) {
    const int tid  = threadIdx.x;          // 512 threads = 16 warps
    const int w    = tid >> 5;
    const int lane = tid & 31;             // float4 column

    float4 acc = make_float4(0.f, 0.f, 0.f, 0.f);
    // warp-strided tiles, 2 independent loads in flight
    int t = w;
    for (; t + 16 < NTILES; t += 32) {
        float4 v0 = __ldg(((const float4*)(g_partials + t * D_DIM)) + lane);
        float4 v1 = __ldg(((const float4*)(g_partials + (t + 16) * D_DIM)) + lane);
        acc.x += v0.x + v1.x; acc.y += v0.y + v1.y;
        acc.z += v0.z + v1.z; acc.w += v0.w + v1.w;
    }
    if (t < NTILES) {
        float4 v = __ldg(((const float4*)(g_partials + t * D_DIM)) + lane);
        acc.x += v.x; acc.y += v.y; acc.z += v.z; acc.w += v.w;
    }

    __shared__ float4 sb[16][32];
    sb[w][lane] = acc;
    __syncthreads();

    if (w == 0) {
        float4 s = sb[0][lane];
        #pragma unroll
        for (int i = 1; i < 16; ++i) {
            float4 v = sb[i][lane];
            s.x += v.x; s.y += v.y; s.z += v.z; s.w += v.w;
        }
        // softmax over 128 logits held as 32 lanes x 4
        float m = fmaxf(fmaxf(s.x, s.y), fmaxf(s.z, s.w));
        #pragma unroll
        for (int off = 16; off > 0; off >>= 1)
            m = fmaxf(m, __shfl_xor_sync(0xffffffffu, m, off));
        float e0 = expf(s.x - m), e1 = expf(s.y - m);
        float e2 = expf(s.z - m), e3 = expf(s.w - m);
        float sum = (e0 + e1) + (e2 + e3);
        #pragma unroll
        for (int off = 16; off > 0; off >>= 1)
            sum += __shfl_xor_sync(0xffffffffu, sum, off);
        float rinv = 1.0f / sum;
        ((float4*)out)[lane] = make_float4(e0 * rinv, e1 * rinv, e2 * rinv, e3 * rinv);
    }
}

// ---------------- launcher --------------------------------------------------
extern "C" void kernel_launch(void* const* d_in, const int* in_sizes, int n_in,
                              void* d_out, int out_size) {
    const int*   node_ids     = (const int*)d_in[0];
    const int*   neighbor_ids = (const int*)d_in[1];
    const int*   segment_ids  = (const int*)d_in[2];
    const float* W            = (const float*)d_in[3];
    const float* M            = (const float*)d_in[4];
    const float* emb          = (const float*)d_in[5];
    float*       out          = (float*)d_out;

    prep_kernel<<<PREP_BLOCKS, 256>>>(emb, W, M, segment_ids);
    fused_kernel<<<NTILES, 512, A_BYTES>>>(node_ids, neighbor_ids);
    final_kernel<<<1, 512>>>(out);
}

// round 6
// speedup vs baseline: 1.0685x; 1.0685x over previous
#include <cuda_runtime.h>
#include <cuda_bf16.h>
#include <mma.h>
#include <math.h>

using namespace nvcuda;

#define D_DIM 128
#define V_DIM 100000
#define N_DIM 20000
#define E_DIM 640000
#define NODES_PER_BLK 64
#define NTILES ((N_DIM + NODES_PER_BLK - 1) / NODES_PER_BLK)   // 313

// padded strides (conflict-free LDSM: 528B row shift = 4 banks)
#define SA 264                 // bf16 elems per A row (528 B)
#define SC 132                 // float elems per C row (528 B)
#define A_BYTES (64 * SA * 2)  // 33792 (== 64*SC*4, C overlays A)

// prep kernel block ranges
#define EPACK_T      800000    // total float4s handled 4-per-thread: 3.2M
#define EPACK_BLOCKS 3125      // 800000 / 256
#define WM_BLOCKS    32
#define RP_BLOCKS    2500
#define PREP_BLOCKS  (EPACK_BLOCKS + WM_BLOCKS + RP_BLOCKS)

// ---------------- scratch (device globals; no runtime allocation) ----------
__device__ int   g_rowptr[N_DIM + 1];
__device__ __nv_bfloat16 g_embh[(size_t)V_DIM * D_DIM];      // 25.6 MB bf16 table
__device__ __nv_bfloat16 g_wm[D_DIM * 2 * D_DIM];            // [128][256] bf16
__device__ float g_partials[NTILES * D_DIM];

// ---------------- K1: prep (pack emb->bf16, pack [W|M], rowptr) ------------
__global__ void prep_kernel(const float* __restrict__ emb,
                            const float* __restrict__ W,
                            const float* __restrict__ M,
                            const int* __restrict__ seg) {
    const int b   = blockIdx.x;
    const int tid = threadIdx.x;

    if (b < EPACK_BLOCKS) {
        // pack embedding table: 4 independent float4->uint2 per thread
        const int t = b * 256 + tid;              // 0 .. 799999
        const float4* src = (const float4*)emb;
        float4 v[4];
        #pragma unroll
        for (int k = 0; k < 4; ++k)
            v[k] = __ldg(src + t + k * EPACK_T);
        #pragma unroll
        for (int k = 0; k < 4; ++k) {
            __nv_bfloat162 lo = __float22bfloat162_rn(make_float2(v[k].x, v[k].y));
            __nv_bfloat162 hi = __float22bfloat162_rn(make_float2(v[k].z, v[k].w));
            uint2 u;
            u.x = *(unsigned int*)&lo;
            u.y = *(unsigned int*)&hi;
            ((uint2*)g_embh)[t + k * EPACK_T] = u;
        }
    } else if (b < EPACK_BLOCKS + WM_BLOCKS) {
        int base = (b - EPACK_BLOCKS) * 256 + tid;
        #pragma unroll
        for (int rep = 0; rep < 4; ++rep) {
            int i = base + rep * 8192;            // 0..32767
            int d = i >> 8;
            int k = i & 255;
            float v = (k < D_DIM) ? __ldg(&W[d * D_DIM + k])
                                  : __ldg(&M[d * D_DIM + (k - D_DIM)]);
            g_wm[i] = __float2bfloat16(v);
        }
    } else {
        int e = (b - EPACK_BLOCKS - WM_BLOCKS) * 256 + tid;
        if (e >= E_DIM) return;
        int s = __ldg(&seg[e]);
        if (e == 0) {
            for (int t = 0; t <= s; ++t) g_rowptr[t] = 0;
        } else {
            int p = __ldg(&seg[e - 1]);
            for (int t = p + 1; t <= s; ++t) g_rowptr[t] = e;
        }
        if (e == E_DIM - 1) {
            for (int t = s + 1; t <= N_DIM; ++t) g_rowptr[t] = E_DIM;
        }
    }
}

// ---------------- helpers ---------------------------------------------------
__device__ __forceinline__ void acc_bf4(float acc[4], uint2 v) {
    float2 f0 = __bfloat1622float2(*(__nv_bfloat162*)&v.x);
    float2 f1 = __bfloat1622float2(*(__nv_bfloat162*)&v.y);
    acc[0] += f0.x; acc[1] += f0.y;
    acc[2] += f1.x; acc[3] += f1.y;
}

__device__ __forceinline__ uint2 pack_bf4(const float acc[4]) {
    __nv_bfloat162 b0 = __float22bfloat162_rn(make_float2(acc[0], acc[1]));
    __nv_bfloat162 b1 = __float22bfloat162_rn(make_float2(acc[2], acc[3]));
    uint2 u;
    u.x = *(unsigned int*)&b0;
    u.y = *(unsigned int*)&b1;
    return u;
}

// ---------------- K2: FUSED gather + segment-sum + GEMM + relu + colsum ----
// One block per 64-node tile, 512 threads = 16 warps.
// Phase 1: warp w owns rows [4w,4w+4). Full warp per edge row: lane = uint2
//   (8B) chunk of the 256B bf16 row. Edge loop unrolled x8 -> 8 independent
//   LDG.64 gathers in flight per warp (2KB outstanding). fp32 accumulate.
// Phase 2: warp w: rows [32(w>>3), +32), cols [16(w&7), +16). B from g_wm.
// Phase 3: relu -> C overlay -> column-sum -> per-block partials.
__global__ __launch_bounds__(512)
void fused_kernel(const int* __restrict__ node_ids,
                  const int* __restrict__ nbr) {
    extern __shared__ unsigned char dynsmem[];
    __nv_bfloat16* As = (__nv_bfloat16*)dynsmem;   // [64][SA]
    float*         Cs = (float*)dynsmem;           // [64][SC] (overlay)
    __shared__ float red[512];

    const int tid  = threadIdx.x;
    const int w    = tid >> 5;
    const int lane = tid & 31;
    const int n0   = blockIdx.x * NODES_PER_BLK;

    // ---------- Phase 1: gather + aggregate into A (bf16 table) ----------
    #pragma unroll
    for (int i = 0; i < 4; ++i) {
        const int r = w * 4 + i;
        const int n = n0 + r;
        const bool valid = (n < N_DIM);

        // self row: straight bf16 copy, 32 lanes x 8B = 256B
        uint2 sv = make_uint2(0, 0);
        if (valid) {
            int nid = __ldg(&node_ids[n]);
            sv = __ldg(((const uint2*)(g_embh + (size_t)nid * D_DIM)) + lane);
        }
        *(uint2*)(As + r * SA + lane * 4) = sv;

        float acc[4] = {0.f, 0.f, 0.f, 0.f};
        if (valid) {
            const int s = g_rowptr[n];
            const int e = g_rowptr[n + 1];
            int j = s;
            for (; j + 8 <= e; j += 8) {
                int ix[8];
                #pragma unroll
                for (int k = 0; k < 8; ++k) ix[k] = __ldg(&nbr[j + k]);
                uint2 v[8];
                #pragma unroll
                for (int k = 0; k < 8; ++k)
                    v[k] = __ldg(((const uint2*)(g_embh + (size_t)ix[k] * D_DIM)) + lane);
                #pragma unroll
                for (int k = 0; k < 8; ++k) acc_bf4(acc, v[k]);
            }
            for (; j < e; ++j) {
                int ix = __ldg(&nbr[j]);
                uint2 v = __ldg(((const uint2*)(g_embh + (size_t)ix * D_DIM)) + lane);
                acc_bf4(acc, v);
            }
        }
        *(uint2*)(As + r * SA + D_DIM + lane * 4) = pack_bf4(acc);
    }
    __syncthreads();

    // ---------- Phase 2: MMA ----------
    const int rb = w >> 3;    // rows [32rb, 32rb+32)
    const int cb = w & 7;     // cols [16cb, 16cb+16)

    wmma::fragment<wmma::accumulator, 16, 16, 16, float> c0f, c1f;
    wmma::fill_fragment(c0f, 0.0f);
    wmma::fill_fragment(c1f, 0.0f);

    #pragma unroll
    for (int kk = 0; kk < 16; ++kk) {
        wmma::fragment<wmma::matrix_b, 16, 16, 16, __nv_bfloat16, wmma::col_major> bf;
        wmma::load_matrix_sync(bf, g_wm + (cb * 16) * 256 + kk * 16, 256);
        wmma::fragment<wmma::matrix_a, 16, 16, 16, __nv_bfloat16, wmma::row_major> a0, a1;
        wmma::load_matrix_sync(a0, As + (rb * 32) * SA + kk * 16, SA);
        wmma::load_matrix_sync(a1, As + (rb * 32 + 16) * SA + kk * 16, SA);
        wmma::mma_sync(c0f, a0, bf, c0f);
        wmma::mma_sync(c1f, a1, bf, c1f);
    }
    __syncthreads();    // all warps done reading A before C overlay

    #pragma unroll
    for (int t = 0; t < c0f.num_elements; ++t) {
        c0f.x[t] = fmaxf(c0f.x[t], 0.0f);
        c1f.x[t] = fmaxf(c1f.x[t], 0.0f);
    }
    wmma::store_matrix_sync(Cs + (rb * 32) * SC + cb * 16, c0f, SC, wmma::mem_row_major);
    wmma::store_matrix_sync(Cs + (rb * 32 + 16) * SC + cb * 16, c1f, SC, wmma::mem_row_major);
    __syncthreads();

    // ---------- Phase 3: column-sum 64x128 -> partials ----------
    {
        const int col  = tid & 127;
        const int part = tid >> 7;        // 0..3 -> 16-row bands
        float s = 0.f;
        #pragma unroll
        for (int rr = part * 16; rr < part * 16 + 16; ++rr)
            s += Cs[rr * SC + col];
        red[tid] = s;
    }
    __syncthreads();
    if (tid < 128)
        g_partials[blockIdx.x * D_DIM + tid] =
            red[tid] + red[tid + 128] + red[tid + 256] + red[tid + 384];
}

// ---------------- K3: reduce partials + softmax (float4, warp-parallel) ----
__global__ void final_kernel(float* __restrict__ out) {
    const int tid  = threadIdx.x;          // 512 threads = 16 warps
    const int w    = tid >> 5;
    const int lane = tid & 31;             // float4 column

    float4 acc = make_float4(0.f, 0.f, 0.f, 0.f);
    int t = w;
    for (; t + 16 < NTILES; t += 32) {
        float4 v0 = __ldg(((const float4*)(g_partials + t * D_DIM)) + lane);
        float4 v1 = __ldg(((const float4*)(g_partials + (t + 16) * D_DIM)) + lane);
        acc.x += v0.x + v1.x; acc.y += v0.y + v1.y;
        acc.z += v0.z + v1.z; acc.w += v0.w + v1.w;
    }
    if (t < NTILES) {
        float4 v = __ldg(((const float4*)(g_partials + t * D_DIM)) + lane);
        acc.x += v.x; acc.y += v.y; acc.z += v.z; acc.w += v.w;
    }

    __shared__ float4 sb[16][32];
    sb[w][lane] = acc;
    __syncthreads();

    if (w == 0) {
        float4 s = sb[0][lane];
        #pragma unroll
        for (int i = 1; i < 16; ++i) {
            float4 v = sb[i][lane];
            s.x += v.x; s.y += v.y; s.z += v.z; s.w += v.w;
        }
        float m = fmaxf(fmaxf(s.x, s.y), fmaxf(s.z, s.w));
        #pragma unroll
        for (int off = 16; off > 0; off >>= 1)
            m = fmaxf(m, __shfl_xor_sync(0xffffffffu, m, off));
        float e0 = expf(s.x - m), e1 = expf(s.y - m);
        float e2 = expf(s.z - m), e3 = expf(s.w - m);
        float sum = (e0 + e1) + (e2 + e3);
        #pragma unroll
        for (int off = 16; off > 0; off >>= 1)
            sum += __shfl_xor_sync(0xffffffffu, sum, off);
        float rinv = 1.0f / sum;
        ((float4*)out)[lane] = make_float4(e0 * rinv, e1 * rinv, e2 * rinv, e3 * rinv);
    }
}

// ---------------- launcher --------------------------------------------------
extern "C" void kernel_launch(void* const* d_in, const int* in_sizes, int n_in,
                              void* d_out, int out_size) {
    const int*   node_ids     = (const int*)d_in[0];
    const int*   neighbor_ids = (const int*)d_in[1];
    const int*   segment_ids  = (const int*)d_in[2];
    const float* W            = (const float*)d_in[3];
    const float* M            = (const float*)d_in[4];
    const float* emb          = (const float*)d_in[5];
    float*       out          = (float*)d_out;

    prep_kernel<<<PREP_BLOCKS, 256>>>(emb, W, M, segment_ids);
    fused_kernel<<<NTILES, 512, A_BYTES>>>(node_ids, neighbor_ids);
    final_kernel<<<1, 512>>>(out);
}

// round 7
// speedup vs baseline: 1.1498x; 1.0762x over previous
#include <cuda_runtime.h>
#include <cuda_bf16.h>
#include <mma.h>
#include <math.h>

using namespace nvcuda;

#define D_DIM 128
#define V_DIM 100000
#define N_DIM 20000
#define E_DIM 640000
#define NODES_PER_BLK 32
#define NTILES (N_DIM / NODES_PER_BLK)     // 625, exact

// padded strides (conflict-free LDSM: 528B row shift = 4 banks)
#define SA 264                  // bf16 elems per A row (528 B)
#define SC 132                  // float elems per C row (528 B)
#define A_BYTES   (NODES_PER_BLK * SA * 2)       // 16896 (== 32*SC*4, C overlay)
#define IDX_CAP   1600                           // staged edge indices (mean 1024, +18 sigma)
#define IDX_BYTES (IDX_CAP * 4)
#define DYN_BYTES (A_BYTES + IDX_BYTES)          // 23296

// prep kernel block ranges
#define EPACK_T      400000     // float4 stride; 8 per thread -> 3.2M total
#define EPACK_BLOCKS 1563       // ceil(400000/256)
#define WM_BLOCKS    32
#define RP_BLOCKS    2500
#define PREP_BLOCKS  (EPACK_BLOCKS + WM_BLOCKS + RP_BLOCKS)

// ---------------- scratch (device globals; no runtime allocation) ----------
__device__ int   g_rowptr[N_DIM + 1];
__device__ __nv_bfloat16 g_embh[(size_t)V_DIM * D_DIM];      // 25.6 MB bf16 table
__device__ __nv_bfloat16 g_wm[D_DIM * 2 * D_DIM];            // [128][256] bf16
__device__ float g_partials[NTILES * D_DIM];

// ---------------- K1: prep (pack emb->bf16, pack [W|M], rowptr) ------------
__global__ void prep_kernel(const float* __restrict__ emb,
                            const float* __restrict__ W,
                            const float* __restrict__ M,
                            const int* __restrict__ seg) {
    const int b   = blockIdx.x;
    const int tid = threadIdx.x;

    if (b < EPACK_BLOCKS) {
        const int t = b * 256 + tid;              // 0 .. 400127
        if (t < EPACK_T) {
            const float4* src = (const float4*)emb;
            float4 v[8];
            #pragma unroll
            for (int k = 0; k < 8; ++k)
                v[k] = __ldg(src + t + k * EPACK_T);
            #pragma unroll
            for (int k = 0; k < 8; ++k) {
                __nv_bfloat162 lo = __float22bfloat162_rn(make_float2(v[k].x, v[k].y));
                __nv_bfloat162 hi = __float22bfloat162_rn(make_float2(v[k].z, v[k].w));
                uint2 u;
                u.x = *(unsigned int*)&lo;
                u.y = *(unsigned int*)&hi;
                ((uint2*)g_embh)[t + k * EPACK_T] = u;
            }
        }
    } else if (b < EPACK_BLOCKS + WM_BLOCKS) {
        int base = (b - EPACK_BLOCKS) * 256 + tid;
        #pragma unroll
        for (int rep = 0; rep < 4; ++rep) {
            int i = base + rep * 8192;            // 0..32767
            int d = i >> 8;
            int k = i & 255;
            float v = (k < D_DIM) ? __ldg(&W[d * D_DIM + k])
                                  : __ldg(&M[d * D_DIM + (k - D_DIM)]);
            g_wm[i] = __float2bfloat16(v);
        }
    } else {
        int e = (b - EPACK_BLOCKS - WM_BLOCKS) * 256 + tid;
        if (e >= E_DIM) return;
        int s = __ldg(&seg[e]);
        if (e == 0) {
            for (int t = 0; t <= s; ++t) g_rowptr[t] = 0;
        } else {
            int p = __ldg(&seg[e - 1]);
            for (int t = p + 1; t <= s; ++t) g_rowptr[t] = e;
        }
        if (e == E_DIM - 1) {
            for (int t = s + 1; t <= N_DIM; ++t) g_rowptr[t] = E_DIM;
        }
    }
}

// ---------------- helpers ---------------------------------------------------
__device__ __forceinline__ void acc_bf4(float acc[4], uint2 v) {
    float2 f0 = __bfloat1622float2(*(__nv_bfloat162*)&v.x);
    float2 f1 = __bfloat1622float2(*(__nv_bfloat162*)&v.y);
    acc[0] += f0.x; acc[1] += f0.y;
    acc[2] += f1.x; acc[3] += f1.y;
}

__device__ __forceinline__ uint2 pack_bf4(const float acc[4]) {
    __nv_bfloat162 b0 = __float22bfloat162_rn(make_float2(acc[0], acc[1]));
    __nv_bfloat162 b1 = __float22bfloat162_rn(make_float2(acc[2], acc[3]));
    uint2 u;
    u.x = *(unsigned int*)&b0;
    u.y = *(unsigned int*)&b1;
    return u;
}

// ---------------- K2: FUSED gather + segment-sum + GEMM + relu + colsum ----
// One block per 32-node tile (N divides exactly), 256 threads = 8 warps.
// Phase 0: stage the tile's contiguous edge-index range into smem (coalesced).
// Phase 1: warp w owns rows [4w,4w+4). Full warp per edge row: lane = uint2
//   (8B) chunk of the 256B bf16 row. Indices come from smem (LDS) -> no
//   global idx->gather chain; edge loop unrolled x8 (8 gathers in flight).
// Phase 2: warp w computes cols [16w,16w+16) x rows 0..31. B from g_wm (L1).
// Phase 3: relu -> C overlay -> column-sum -> per-block partials.
__global__ __launch_bounds__(256)
void fused_kernel(const int* __restrict__ node_ids,
                  const int* __restrict__ nbr) {
    extern __shared__ unsigned char dynsmem[];
    __nv_bfloat16* As    = (__nv_bfloat16*)dynsmem;        // [32][SA]
    float*         Cs    = (float*)dynsmem;                // [32][SC] (overlay)
    int*           idx_s = (int*)(dynsmem + A_BYTES);      // [IDX_CAP]
    __shared__ float red[256];

    const int tid  = threadIdx.x;
    const int w    = tid >> 5;
    const int lane = tid & 31;
    const int n0   = blockIdx.x * NODES_PER_BLK;

    // ---------- Phase 0: stage edge indices ----------
    const int estart = g_rowptr[n0];
    const int ecnt   = g_rowptr[n0 + NODES_PER_BLK] - estart;
    const int scnt   = (ecnt < IDX_CAP) ? ecnt : IDX_CAP;
    for (int j = tid; j < scnt; j += 256)
        idx_s[j] = __ldg(&nbr[estart + j]);
    __syncthreads();

    // ---------- Phase 1: gather + aggregate into A ----------
    #pragma unroll
    for (int i = 0; i < 4; ++i) {
        const int r = w * 4 + i;
        const int n = n0 + r;

        // self row: straight bf16 copy, 32 lanes x 8B = 256B
        {
            int nid = __ldg(&node_ids[n]);
            uint2 sv = __ldg(((const uint2*)(g_embh + (size_t)nid * D_DIM)) + lane);
            *(uint2*)(As + r * SA + lane * 4) = sv;
        }

        float acc[4] = {0.f, 0.f, 0.f, 0.f};
        const int js = g_rowptr[n]     - estart;
        const int je = g_rowptr[n + 1] - estart;
        int j = js;
        for (; j + 8 <= je; j += 8) {
            int ix[8];
            #pragma unroll
            for (int k = 0; k < 8; ++k) {
                int jj = j + k;
                ix[k] = (jj < IDX_CAP) ? idx_s[jj] : __ldg(&nbr[estart + jj]);
            }
            uint2 v[8];
            #pragma unroll
            for (int k = 0; k < 8; ++k)
                v[k] = __ldg(((const uint2*)(g_embh + (size_t)ix[k] * D_DIM)) + lane);
            #pragma unroll
            for (int k = 0; k < 8; ++k) acc_bf4(acc, v[k]);
        }
        for (; j < je; ++j) {
            int ix = (j < IDX_CAP) ? idx_s[j] : __ldg(&nbr[estart + j]);
            uint2 v = __ldg(((const uint2*)(g_embh + (size_t)ix * D_DIM)) + lane);
            acc_bf4(acc, v);
        }
        *(uint2*)(As + r * SA + D_DIM + lane * 4) = pack_bf4(acc);
    }
    __syncthreads();

    // ---------- Phase 2: MMA (8 warps; warp w -> cols [16w,16w+16)) ----------
    wmma::fragment<wmma::accumulator, 16, 16, 16, float> c0f, c1f;
    wmma::fill_fragment(c0f, 0.0f);
    wmma::fill_fragment(c1f, 0.0f);

    #pragma unroll
    for (int kk = 0; kk < 16; ++kk) {
        wmma::fragment<wmma::matrix_b, 16, 16, 16, __nv_bfloat16, wmma::col_major> bf;
        wmma::load_matrix_sync(bf, g_wm + (w * 16) * 256 + kk * 16, 256);
        wmma::fragment<wmma::matrix_a, 16, 16, 16, __nv_bfloat16, wmma::row_major> a0, a1;
        wmma::load_matrix_sync(a0, As + kk * 16, SA);          // rows 0-15
        wmma::load_matrix_sync(a1, As + 16 * SA + kk * 16, SA); // rows 16-31
        wmma::mma_sync(c0f, a0, bf, c0f);
        wmma::mma_sync(c1f, a1, bf, c1f);
    }
    __syncthreads();    // all warps done reading A before C overlay

    #pragma unroll
    for (int t = 0; t < c0f.num_elements; ++t) {
        c0f.x[t] = fmaxf(c0f.x[t], 0.0f);
        c1f.x[t] = fmaxf(c1f.x[t], 0.0f);
    }
    wmma::store_matrix_sync(Cs + w * 16, c0f, SC, wmma::mem_row_major);
    wmma::store_matrix_sync(Cs + 16 * SC + w * 16, c1f, SC, wmma::mem_row_major);
    __syncthreads();

    // ---------- Phase 3: column-sum 32x128 -> partials ----------
    {
        const int col  = tid & 127;
        const int part = tid >> 7;        // 0/1 -> 16-row bands
        float s = 0.f;
        #pragma unroll
        for (int rr = part * 16; rr < part * 16 + 16; ++rr)
            s += Cs[rr * SC + col];
        red[tid] = s;
    }
    __syncthreads();
    if (tid < 128)
        g_partials[blockIdx.x * D_DIM + tid] = red[tid] + red[tid + 128];
}

// ---------------- K3: reduce partials + softmax (float4, warp-parallel) ----
__global__ void final_kernel(float* __restrict__ out) {
    const int tid  = threadIdx.x;          // 512 threads = 16 warps
    const int w    = tid >> 5;
    const int lane = tid & 31;             // float4 column

    float4 acc = make_float4(0.f, 0.f, 0.f, 0.f);
    int t = w;
    for (; t + 16 < NTILES; t += 32) {
        float4 v0 = __ldg(((const float4*)(g_partials + t * D_DIM)) + lane);
        float4 v1 = __ldg(((const float4*)(g_partials + (t + 16) * D_DIM)) + lane);
        acc.x += v0.x + v1.x; acc.y += v0.y + v1.y;
        acc.z += v0.z + v1.z; acc.w += v0.w + v1.w;
    }
    if (t < NTILES) {
        float4 v = __ldg(((const float4*)(g_partials + t * D_DIM)) + lane);
        acc.x += v.x; acc.y += v.y; acc.z += v.z; acc.w += v.w;
    }

    __shared__ float4 sb[16][32];
    sb[w][lane] = acc;
    __syncthreads();

    if (w == 0) {
        float4 s = sb[0][lane];
        #pragma unroll
        for (int i = 1; i < 16; ++i) {
            float4 v = sb[i][lane];
            s.x += v.x; s.y += v.y; s.z += v.z; s.w += v.w;
        }
        float m = fmaxf(fmaxf(s.x, s.y), fmaxf(s.z, s.w));
        #pragma unroll
        for (int off = 16; off > 0; off >>= 1)
            m = fmaxf(m, __shfl_xor_sync(0xffffffffu, m, off));
        float e0 = expf(s.x - m), e1 = expf(s.y - m);
        float e2 = expf(s.z - m), e3 = expf(s.w - m);
        float sum = (e0 + e1) + (e2 + e3);
        #pragma unroll
        for (int off = 16; off > 0; off >>= 1)
            sum += __shfl_xor_sync(0xffffffffu, sum, off);
        float rinv = 1.0f / sum;
        ((float4*)out)[lane] = make_float4(e0 * rinv, e1 * rinv, e2 * rinv, e3 * rinv);
    }
}

// ---------------- launcher --------------------------------------------------
extern "C" void kernel_launch(void* const* d_in, const int* in_sizes, int n_in,
                              void* d_out, int out_size) {
    const int*   node_ids     = (const int*)d_in[0];
    const int*   neighbor_ids = (const int*)d_in[1];
    const int*   segment_ids  = (const int*)d_in[2];
    const float* W            = (const float*)d_in[3];
    const float* M            = (const float*)d_in[4];
    const float* emb          = (const float*)d_in[5];
    float*       out          = (float*)d_out;

    prep_kernel<<<PREP_BLOCKS, 256>>>(emb, W, M, segment_ids);
    fused_kernel<<<NTILES, 256, DYN_BYTES>>>(node_ids, neighbor_ids);
    final_kernel<<<1, 512>>>(out);
}

// round 8
// speedup vs baseline: 1.2145x; 1.0562x over previous
#include <cuda_runtime.h>
#include <cuda_bf16.h>
#include <mma.h>
#include <math.h>

using namespace nvcuda;

#define D_DIM 128
#define V_DIM 100000
#define N_DIM 20000
#define E_DIM 640000
#define NODES_PER_BLK 32
#define NTILES (N_DIM / NODES_PER_BLK)     // 625, exact

// padded strides (conflict-free LDSM: 528B row shift = 4 banks)
#define SA 264                  // bf16 elems per A row (528 B)
#define SC 132                  // float elems per C row (528 B)
#define A_BYTES   (NODES_PER_BLK * SA * 2)       // 16896 (== 32*SC*4, C overlay)
#define IDX_CAP   1600                           // staged edge indices (mean 1024)
#define IDX_BYTES (IDX_CAP * 4)
#define DYN_BYTES (A_BYTES + IDX_BYTES)          // 23296

// prep kernel block ranges
#define EPACK_T      400000     // float4 stride; 8 per thread -> 3.2M total
#define EPACK_BLOCKS 1563       // ceil(400000/256)
#define WM_BLOCKS    32
#define RP_BLOCKS    2500
#define PREP_BLOCKS  (EPACK_BLOCKS + WM_BLOCKS + RP_BLOCKS)

// ---------------- scratch (device globals; no runtime allocation) ----------
__device__ int   g_rowptr[N_DIM + 1];
__device__ __nv_bfloat16 g_embh[(size_t)V_DIM * D_DIM];      // 25.6 MB bf16 table
__device__ __nv_bfloat16 g_wm[D_DIM * 2 * D_DIM];            // [128][256] bf16
__device__ float g_partials[NTILES * D_DIM];

// ---------------- K1: prep (pack emb->bf16, pack [W|M], rowptr) ------------
__global__ void prep_kernel(const float* __restrict__ emb,
                            const float* __restrict__ W,
                            const float* __restrict__ M,
                            const int* __restrict__ seg) {
    const int b   = blockIdx.x;
    const int tid = threadIdx.x;

    if (b < EPACK_BLOCKS) {
        const int t = b * 256 + tid;              // 0 .. 400127
        if (t < EPACK_T) {
            const float4* src = (const float4*)emb;
            float4 v[8];
            #pragma unroll
            for (int k = 0; k < 8; ++k)
                v[k] = __ldg(src + t + k * EPACK_T);
            #pragma unroll
            for (int k = 0; k < 8; ++k) {
                __nv_bfloat162 lo = __float22bfloat162_rn(make_float2(v[k].x, v[k].y));
                __nv_bfloat162 hi = __float22bfloat162_rn(make_float2(v[k].z, v[k].w));
                uint2 u;
                u.x = *(unsigned int*)&lo;
                u.y = *(unsigned int*)&hi;
                ((uint2*)g_embh)[t + k * EPACK_T] = u;
            }
        }
    } else if (b < EPACK_BLOCKS + WM_BLOCKS) {
        int base = (b - EPACK_BLOCKS) * 256 + tid;
        #pragma unroll
        for (int rep = 0; rep < 4; ++rep) {
            int i = base + rep * 8192;            // 0..32767
            int d = i >> 8;
            int k = i & 255;
            float v = (k < D_DIM) ? __ldg(&W[d * D_DIM + k])
                                  : __ldg(&M[d * D_DIM + (k - D_DIM)]);
            g_wm[i] = __float2bfloat16(v);
        }
    } else {
        int e = (b - EPACK_BLOCKS - WM_BLOCKS) * 256 + tid;
        if (e >= E_DIM) return;
        int s = __ldg(&seg[e]);
        if (e == 0) {
            for (int t = 0; t <= s; ++t) g_rowptr[t] = 0;
        } else {
            int p = __ldg(&seg[e - 1]);
            for (int t = p + 1; t <= s; ++t) g_rowptr[t] = e;
        }
        if (e == E_DIM - 1) {
            for (int t = s + 1; t <= N_DIM; ++t) g_rowptr[t] = E_DIM;
        }
    }
}

// ---------------- helpers ---------------------------------------------------
__device__ __forceinline__ void acc_bf4(float acc[4], uint2 v) {
    float2 f0 = __bfloat1622float2(*(__nv_bfloat162*)&v.x);
    float2 f1 = __bfloat1622float2(*(__nv_bfloat162*)&v.y);
    acc[0] += f0.x; acc[1] += f0.y;
    acc[2] += f1.x; acc[3] += f1.y;
}

__device__ __forceinline__ uint2 pack_bf4(const float acc[4]) {
    __nv_bfloat162 b0 = __float22bfloat162_rn(make_float2(acc[0], acc[1]));
    __nv_bfloat162 b1 = __float22bfloat162_rn(make_float2(acc[2], acc[3]));
    uint2 u;
    u.x = *(unsigned int*)&b0;
    u.y = *(unsigned int*)&b1;
    return u;
}

// ---------------- K2: FUSED gather + segment-sum + GEMM + relu + colsum ----
// One block per 32-node tile, 256 threads = 8 warps.
// Phase 0: stage the tile's contiguous edge-index range into smem.
// Phase 1: warp w owns rows [4w,4w+4). Full warp per edge row: lane = uint2
//   (8B) chunk of the 256B bf16 row. Edge loop unrolled x16: 16 independent
//   LDG.64 gathers in flight per warp (4KB outstanding) -> latency hidden,
//   gather runs at the L2-BW floor. Indices from smem (no global idx chain).
// Phase 2: warp w computes cols [16w,16w+16) x rows 0..31. B from g_wm (L1).
// Phase 3: relu -> C overlay -> column-sum -> per-block partials.
__global__ __launch_bounds__(256)
void fused_kernel(const int* __restrict__ node_ids,
                  const int* __restrict__ nbr) {
    extern __shared__ unsigned char dynsmem[];
    __nv_bfloat16* As    = (__nv_bfloat16*)dynsmem;        // [32][SA]
    float*         Cs    = (float*)dynsmem;                // [32][SC] (overlay)
    int*           idx_s = (int*)(dynsmem + A_BYTES);      // [IDX_CAP]
    __shared__ float red[256];

    const int tid  = threadIdx.x;
    const int w    = tid >> 5;
    const int lane = tid & 31;
    const int n0   = blockIdx.x * NODES_PER_BLK;

    // ---------- Phase 0: stage edge indices ----------
    const int estart = g_rowptr[n0];
    const int ecnt   = g_rowptr[n0 + NODES_PER_BLK] - estart;
    const bool all_staged = (ecnt <= IDX_CAP);
    const int scnt   = all_staged ? ecnt : IDX_CAP;
    for (int j = tid; j < scnt; j += 256)
        idx_s[j] = __ldg(&nbr[estart + j]);
    __syncthreads();

    // ---------- Phase 1: gather + aggregate into A ----------
    #pragma unroll
    for (int i = 0; i < 4; ++i) {
        const int r = w * 4 + i;
        const int n = n0 + r;

        // self row: straight bf16 copy, 32 lanes x 8B = 256B
        {
            int nid = __ldg(&node_ids[n]);
            uint2 sv = __ldg(((const uint2*)(g_embh + (size_t)nid * D_DIM)) + lane);
            *(uint2*)(As + r * SA + lane * 4) = sv;
        }

        float acc[4] = {0.f, 0.f, 0.f, 0.f};
        const int js = g_rowptr[n]     - estart;
        const int je = g_rowptr[n + 1] - estart;

        if (all_staged) {
            int j = js;
            // 16 independent gathers in flight
            for (; j + 16 <= je; j += 16) {
                int ix[16];
                #pragma unroll
                for (int k = 0; k < 16; ++k) ix[k] = idx_s[j + k];
                uint2 v[16];
                #pragma unroll
                for (int k = 0; k < 16; ++k)
                    v[k] = __ldg(((const uint2*)(g_embh + (size_t)ix[k] * D_DIM)) + lane);
                #pragma unroll
                for (int k = 0; k < 16; ++k) acc_bf4(acc, v[k]);
            }
            for (; j + 4 <= je; j += 4) {
                int ix[4];
                #pragma unroll
                for (int k = 0; k < 4; ++k) ix[k] = idx_s[j + k];
                uint2 v[4];
                #pragma unroll
                for (int k = 0; k < 4; ++k)
                    v[k] = __ldg(((const uint2*)(g_embh + (size_t)ix[k] * D_DIM)) + lane);
                #pragma unroll
                for (int k = 0; k < 4; ++k) acc_bf4(acc, v[k]);
            }
            for (; j < je; ++j) {
                uint2 v = __ldg(((const uint2*)(g_embh + (size_t)idx_s[j] * D_DIM)) + lane);
                acc_bf4(acc, v);
            }
        } else {
            // cold path: tile exceeded staging capacity
            for (int j = js; j < je; ++j) {
                int ix = (j < IDX_CAP) ? idx_s[j] : __ldg(&nbr[estart + j]);
                uint2 v = __ldg(((const uint2*)(g_embh + (size_t)ix * D_DIM)) + lane);
                acc_bf4(acc, v);
            }
        }
        *(uint2*)(As + r * SA + D_DIM + lane * 4) = pack_bf4(acc);
    }
    __syncthreads();

    // ---------- Phase 2: MMA (8 warps; warp w -> cols [16w,16w+16)) ----------
    wmma::fragment<wmma::accumulator, 16, 16, 16, float> c0f, c1f;
    wmma::fill_fragment(c0f, 0.0f);
    wmma::fill_fragment(c1f, 0.0f);

    #pragma unroll
    for (int kk = 0; kk < 16; ++kk) {
        wmma::fragment<wmma::matrix_b, 16, 16, 16, __nv_bfloat16, wmma::col_major> bf;
        wmma::load_matrix_sync(bf, g_wm + (w * 16) * 256 + kk * 16, 256);
        wmma::fragment<wmma::matrix_a, 16, 16, 16, __nv_bfloat16, wmma::row_major> a0, a1;
        wmma::load_matrix_sync(a0, As + kk * 16, SA);           // rows 0-15
        wmma::load_matrix_sync(a1, As + 16 * SA + kk * 16, SA); // rows 16-31
        wmma::mma_sync(c0f, a0, bf, c0f);
        wmma::mma_sync(c1f, a1, bf, c1f);
    }
    __syncthreads();    // all warps done reading A before C overlay

    #pragma unroll
    for (int t = 0; t < c0f.num_elements; ++t) {
        c0f.x[t] = fmaxf(c0f.x[t], 0.0f);
        c1f.x[t] = fmaxf(c1f.x[t], 0.0f);
    }
    wmma::store_matrix_sync(Cs + w * 16, c0f, SC, wmma::mem_row_major);
    wmma::store_matrix_sync(Cs + 16 * SC + w * 16, c1f, SC, wmma::mem_row_major);
    __syncthreads();

    // ---------- Phase 3: column-sum 32x128 -> partials ----------
    {
        const int col  = tid & 127;
        const int part = tid >> 7;        // 0/1 -> 16-row bands
        float s = 0.f;
        #pragma unroll
        for (int rr = part * 16; rr < part * 16 + 16; ++rr)
            s += Cs[rr * SC + col];
        red[tid] = s;
    }
    __syncthreads();
    if (tid < 128)
        g_partials[blockIdx.x * D_DIM + tid] = red[tid] + red[tid + 128];
}

// ---------------- K3: reduce partials + softmax (float4, warp-parallel) ----
__global__ void final_kernel(float* __restrict__ out) {
    const int tid  = threadIdx.x;          // 512 threads = 16 warps
    const int w    = tid >> 5;
    const int lane = tid & 31;             // float4 column

    float4 acc = make_float4(0.f, 0.f, 0.f, 0.f);
    int t = w;
    for (; t + 16 < NTILES; t += 32) {
        float4 v0 = __ldg(((const float4*)(g_partials + t * D_DIM)) + lane);
        float4 v1 = __ldg(((const float4*)(g_partials + (t + 16) * D_DIM)) + lane);
        acc.x += v0.x + v1.x; acc.y += v0.y + v1.y;
        acc.z += v0.z + v1.z; acc.w += v0.w + v1.w;
    }
    if (t < NTILES) {
        float4 v = __ldg(((const float4*)(g_partials + t * D_DIM)) + lane);
        acc.x += v.x; acc.y += v.y; acc.z += v.z; acc.w += v.w;
    }

    __shared__ float4 sb[16][32];
    sb[w][lane] = acc;
    __syncthreads();

    if (w == 0) {
        float4 s = sb[0][lane];
        #pragma unroll
        for (int i = 1; i < 16; ++i) {
            float4 v = sb[i][lane];
            s.x += v.x; s.y += v.y; s.z += v.z; s.w += v.w;
        }
        float m = fmaxf(fmaxf(s.x, s.y), fmaxf(s.z, s.w));
        #pragma unroll
        for (int off = 16; off > 0; off >>= 1)
            m = fmaxf(m, __shfl_xor_sync(0xffffffffu, m, off));
        float e0 = expf(s.x - m), e1 = expf(s.y - m);
        float e2 = expf(s.z - m), e3 = expf(s.w - m);
        float sum = (e0 + e1) + (e2 + e3);
        #pragma unroll
        for (int off = 16; off > 0; off >>= 1)
            sum += __shfl_xor_sync(0xffffffffu, sum, off);
        float rinv = 1.0f / sum;
        ((float4*)out)[lane] = make_float4(e0 * rinv, e1 * rinv, e2 * rinv, e3 * rinv);
    }
}

// ---------------- launcher --------------------------------------------------
extern "C" void kernel_launch(void* const* d_in, const int* in_sizes, int n_in,
                              void* d_out, int out_size) {
    const int*   node_ids     = (const int*)d_in[0];
    const int*   neighbor_ids = (const int*)d_in[1];
    const int*   segment_ids  = (const int*)d_in[2];
    const float* W            = (const float*)d_in[3];
    const float* M            = (const float*)d_in[4];
    const float* emb          = (const float*)d_in[5];
    float*       out          = (float*)d_out;

    prep_kernel<<<PREP_BLOCKS, 256>>>(emb, W, M, segment_ids);
    fused_kernel<<<NTILES, 256, DYN_BYTES>>>(node_ids, neighbor_ids);
    final_kernel<<<1, 512>>>(out);
}